// round 16
// baseline (speedup 1.0000x reference)
#include <cuda_runtime.h>
#include <cuda_bf16.h>
#include <cstdint>

// Problem constants (fixed shapes from the reference)
#define Bc     4
#define Sc     2048
#define Dc     512
#define Mc     2048          // clip range
#define Vc     4097          // 2M+1 table rows
#define PMAX   3000          // positions in [0, 3000)
#define NFFT   8192
#define CPAIRS (Dc/2)        // 256 complex-packed channel pairs
#define FFT_THREADS 512
#define LUT_N  1024                          // u = W^jm, jm < NFFT/8 (fp32)
#define PADN   (NFFT + (NFFT >> 5))          // 8448 u32 per buffer
#define MAP(i) ((i) + ((i) >> 5))            // bank-conflict-free pad (4B elems)
#define FFT_SMEM (2 * PADN * 4 + LUT_N * 8)  // 75776 B -> 2 CTAs/SM

// ---------------------------------------------------------------------------
// Scratch (static device globals)
// ---------------------------------------------------------------------------
__device__ float    g_pre[Bc][PMAX];          // inclusive prefix sums of counts
__device__ uint32_t g_CNT[Bc][NFFT];          // spectra of cnt (bf16x2: re,im)
__device__ uint32_t g_EMB[CPAIRS][NFFT];      // spectra of table column pairs
__device__ uint32_t g_EbfT[CPAIRS][NFFT];     // transposed packed emb columns
__device__ uint32_t g_Gp[Bc][PMAX][CPAIRS];   // interior result, packed bf16x2

// ---------------------------------------------------------------------------
// bf16x2 <-> float2 (re in low half, im in high half)
// ---------------------------------------------------------------------------
__device__ __forceinline__ float2 up(uint32_t v) {
    return make_float2(__uint_as_float(v << 16),
                       __uint_as_float(v & 0xFFFF0000u));
}
__device__ __forceinline__ uint32_t pk(float2 f) {
    uint32_t r;
    asm("cvt.rn.bf16x2.f32 %0, %1, %2;" : "=r"(r) : "f"(f.y), "f"(f.x));
    return r;
}

__device__ __forceinline__ float2 cmul(float2 a, float2 b) {
    return make_float2(a.x * b.x - a.y * b.y, a.x * b.y + a.y * b.x);
}
__device__ __forceinline__ float2 cadd(float2 a, float2 b) {
    return make_float2(a.x + b.x, a.y + b.y);
}
__device__ __forceinline__ float2 csub(float2 a, float2 b) {
    return make_float2(a.x - b.x, a.y - b.y);
}
template <bool INV>
__device__ __forceinline__ float2 mul_mi(float2 v) {   // * (-i) fwd, (+i) inv
    return INV ? make_float2(-v.y, v.x) : make_float2(v.y, -v.x);
}
#define RSQRT2 0.70710678118654752f
template <bool INV>
__device__ __forceinline__ float2 mul_w1(float2 v) {
    return INV ? make_float2((v.x - v.y) * RSQRT2, (v.y + v.x) * RSQRT2)
               : make_float2((v.x + v.y) * RSQRT2, (v.y - v.x) * RSQRT2);
}
template <bool INV>
__device__ __forceinline__ float2 mul_w3(float2 v) {
    return INV ? make_float2((-v.x - v.y) * RSQRT2, (v.x - v.y) * RSQRT2)
               : make_float2((v.y - v.x) * RSQRT2, (-v.x - v.y) * RSQRT2);
}

// ---------------------------------------------------------------------------
// Twiddle LUT (fp32): lut[t] = exp(-2*pi*i*t/NFFT), t in [0, NFFT/8)
// ---------------------------------------------------------------------------
__device__ __forceinline__ void build_lut(float2* lut) {
    const float w = -6.283185307179586f / (float)NFFT;
#pragma unroll
    for (int h = 0; h < LUT_N / FFT_THREADS; h++) {
        const int t = threadIdx.x + h * FFT_THREADS;
        float sn, cs;
        __sincosf(w * (float)t, &sn, &cs);
        lut[t] = make_float2(cs, sn);
    }
}

// ---------------------------------------------------------------------------
// Radix-8 core (no twiddles)
// ---------------------------------------------------------------------------
template <bool INV>
__device__ __forceinline__ void bf8_core(float2 y[8],
                                         float2 x0, float2 x1, float2 x2, float2 x3,
                                         float2 x4, float2 x5, float2 x6, float2 x7) {
    const float2 t0 = cadd(x0, x4);
    const float2 t1 = csub(x0, x4);
    const float2 t2 = cadd(x2, x6);
    const float2 t3 = mul_mi<INV>(csub(x2, x6));
    const float2 E0 = cadd(t0, t2);
    const float2 E1 = cadd(t1, t3);
    const float2 E2 = csub(t0, t2);
    const float2 E3 = csub(t1, t3);
    const float2 s0 = cadd(x1, x5);
    const float2 s1 = csub(x1, x5);
    const float2 s2 = cadd(x3, x7);
    const float2 s3 = mul_mi<INV>(csub(x3, x7));
    const float2 O0 = cadd(s0, s2);
    const float2 O1 = mul_w1<INV>(cadd(s1, s3));
    const float2 O2 = mul_mi<INV>(csub(s0, s2));
    const float2 O3 = mul_w3<INV>(csub(s1, s3));
    y[0] = cadd(E0, O0); y[1] = cadd(E1, O1);
    y[2] = cadd(E2, O2); y[3] = cadd(E3, O3);
    y[4] = csub(E0, O0); y[5] = csub(E1, O1);
    y[6] = csub(E2, O2); y[7] = csub(E3, O3);
}

// ---------------------------------------------------------------------------
// Radix-8 butterfly -> smem.
// ---------------------------------------------------------------------------
template <bool INV>
__device__ __forceinline__ void bf8(uint32_t* dst, int t, int m,
                                    float2 x0, float2 x1, float2 x2, float2 x3,
                                    float2 x4, float2 x5, float2 x6, float2 x7,
                                    const float2* __restrict__ lut) {
    const int k  = t & (m - 1);
    const int jm = t - k;
    float2 y[8];
    bf8_core<INV>(y, x0, x1, x2, x3, x4, x5, x6, x7);

    float2 u = lut[jm];
    if (INV) u.y = -u.y;
    const float2 u2 = cmul(u, u);
    const float2 u3 = cmul(u2, u);
    const float2 u4 = cmul(u2, u2);

    const int ob = t + 7 * jm;             // 8*j*m + k
    dst[MAP(ob + 0 * m)] = pk(y[0]);
    dst[MAP(ob + 1 * m)] = pk(cmul(u,  y[1]));
    dst[MAP(ob + 2 * m)] = pk(cmul(u2, y[2]));
    dst[MAP(ob + 3 * m)] = pk(cmul(u3, y[3]));
    dst[MAP(ob + 4 * m)] = pk(cmul(u4, y[4]));
    dst[MAP(ob + 5 * m)] = pk(cmul(cmul(u4, u),  y[5]));
    dst[MAP(ob + 6 * m)] = pk(cmul(cmul(u4, u2), y[6]));
    dst[MAP(ob + 7 * m)] = pk(cmul(cmul(u4, u3), y[7]));
}

// middle stage: smem -> smem (fully unrolled: keep 2-butterfly ILP)
template <bool INV>
__device__ __forceinline__ void stage_smem(const uint32_t* src, uint32_t* dst,
                                           int m, const float2* __restrict__ lut) {
#pragma unroll
    for (int h = 0; h < 2; h++) {
        const int t = threadIdx.x + h * FFT_THREADS;   // [0, 1024)
        bf8<INV>(dst, t, m,
                 up(src[MAP(t + 0 * 1024)]), up(src[MAP(t + 1 * 1024)]),
                 up(src[MAP(t + 2 * 1024)]), up(src[MAP(t + 3 * 1024)]),
                 up(src[MAP(t + 4 * 1024)]), up(src[MAP(t + 5 * 1024)]),
                 up(src[MAP(t + 6 * 1024)]), up(src[MAP(t + 7 * 1024)]),
                 lut);
    }
}

// ---------------------------------------------------------------------------
// Fused last pass: stage 3 (m=512, j=0 & j=1 in registers) + final radix-2.
// j=1 twiddle W^512r = exp(-i*pi*r/8): compile-time constants.
// PRUNE: skip r in {2,3}.
// ---------------------------------------------------------------------------
template <bool INV, bool PRUNE>
__device__ __forceinline__ void last_pass(const uint32_t* src,
                                          float2 sum[8], float2 dif[8]) {
    const int k = threadIdx.x;
    float2 A[8];
    bf8_core<INV>(A,
                  up(src[MAP(k + 0 * 1024)]), up(src[MAP(k + 1 * 1024)]),
                  up(src[MAP(k + 2 * 1024)]), up(src[MAP(k + 3 * 1024)]),
                  up(src[MAP(k + 4 * 1024)]), up(src[MAP(k + 5 * 1024)]),
                  up(src[MAP(k + 6 * 1024)]), up(src[MAP(k + 7 * 1024)]));
    float2 B[8];
    {
        const int t = k + 512;
        bf8_core<INV>(B,
                      up(src[MAP(t + 0 * 1024)]), up(src[MAP(t + 1 * 1024)]),
                      up(src[MAP(t + 2 * 1024)]), up(src[MAP(t + 3 * 1024)]),
                      up(src[MAP(t + 4 * 1024)]), up(src[MAP(t + 5 * 1024)]),
                      up(src[MAP(t + 6 * 1024)]), up(src[MAP(t + 7 * 1024)]));
    }
    const float TWC[8] = { 1.0f,  0.92387953251f,  0.70710678119f,  0.38268343236f,
                           0.0f, -0.38268343236f, -0.70710678119f, -0.92387953251f };
    const float TWS[8] = { 0.0f, -0.38268343236f, -0.70710678119f, -0.92387953251f,
                          -1.0f, -0.92387953251f, -0.70710678119f, -0.38268343236f };
#pragma unroll
    for (int r = 0; r < 8; r++) {
        if (PRUNE && (r == 2 || r == 3)) continue;
        const float2 w  = make_float2(TWC[r], INV ? -TWS[r] : TWS[r]);
        const float2 Br = cmul(w, B[r]);
        sum[r] = cadd(A[r], Br);
        dif[r] = csub(A[r], Br);
    }
}

extern __shared__ uint32_t smu[];

// ---------------------------------------------------------------------------
// K0: transpose emb [4097][512] fp32 -> g_EbfT[c][n] packed bf16x2, zero-pad
// ---------------------------------------------------------------------------
__global__ void transpose_kernel(const float* __restrict__ emb) {
    __shared__ uint32_t tile[32][33];
    const int n0 = blockIdx.x * 32;
    const int c0 = blockIdx.y * 32;
    const int tx = threadIdx.x;
    for (int r = threadIdx.y; r < 32; r += 8) {
        const int n = n0 + r;
        uint32_t v = 0;
        if (n < Vc) {
            const float2 e = *reinterpret_cast<const float2*>(
                &emb[n * Dc + 2 * (c0 + tx)]);
            v = pk(e);
        }
        tile[r][tx] = v;
    }
    __syncthreads();
    for (int r = threadIdx.y; r < 32; r += 8)
        g_EbfT[c0 + r][n0 + tx] = tile[tx][r];
}

// ---------------------------------------------------------------------------
// K1 (merged prep): grid = CPAIRS + Bc blocks.
// ---------------------------------------------------------------------------
__global__ void __launch_bounds__(FFT_THREADS, 2)
prep_kernel(const int* __restrict__ pos) {
    uint32_t* b0  = smu;
    uint32_t* b1  = smu + PADN;
    float2*   lut = (float2*)(smu + 2 * PADN);

    if (blockIdx.x < CPAIRS) {
        const int c = blockIdx.x;
        build_lut(lut);
        __syncthreads();

        const uint32_t* __restrict__ Ec = g_EbfT[c];
        // stage 0 (m=1) fused with coalesced global load
#pragma unroll
        for (int h = 0; h < 2; h++) {
            const int t = threadIdx.x + h * FFT_THREADS;
            float2 z[8];
#pragma unroll
            for (int r = 0; r < 8; r++)
                z[r] = up(Ec[t + r * 1024]);
            bf8<false>(b0, t, 1, z[0], z[1], z[2], z[3], z[4], z[5], z[6], z[7], lut);
        }
        __syncthreads();
        stage_smem<false>(b0, b1, 8, lut);   __syncthreads();
        stage_smem<false>(b1, b0, 64, lut);  __syncthreads();

        // fused stage3 + radix-2 -> global
        float2 sum[8], dif[8];
        last_pass<false, false>(b0, sum, dif);
        const int k = threadIdx.x;
#pragma unroll
        for (int r = 0; r < 8; r++) {
            const int i = k + r * 512;
            g_EMB[c][i]        = pk(sum[r]);
            g_EMB[c][i + 4096] = pk(dif[r]);
        }
        return;
    }

    // ---------------- count-histogram blocks ----------------
    const int b = blockIdx.x - CPAIRS;
    const int t = threadIdx.x;
    float* hist = (float*)b1;        // 3072 floats in b1 region
    float* tsum = (float*)b0;        // 512 partial sums in b0 region

    for (int p = t; p < 3072; p += FFT_THREADS) hist[p] = 0.0f;
    __syncthreads();
    for (int i = t; i < Sc; i += FFT_THREADS)
        atomicAdd(&hist[pos[b * Sc + i]], 1.0f);
    __syncthreads();

    // inclusive prefix scan: 6 bins per thread
    float v[6];
    float s = 0.0f;
#pragma unroll
    for (int j = 0; j < 6; j++) { v[j] = hist[6 * t + j]; s += v[j]; }
    tsum[t] = s;
    __syncthreads();
    for (int off = 1; off < FFT_THREADS; off <<= 1) {
        const float add = (t >= off) ? tsum[t - off] : 0.0f;
        __syncthreads();
        tsum[t] += add;
        __syncthreads();
    }
    float run = tsum[t] - s;   // exclusive
#pragma unroll
    for (int j = 0; j < 6; j++) {
        run += v[j];
        const int p = 6 * t + j;
        if (p < PMAX) g_pre[b][p] = run;
    }
    __syncthreads();

    // forward FFT of the histogram (stage0 reads hist directly from smem)
    build_lut(lut);
    __syncthreads();
#pragma unroll
    for (int h = 0; h < 2; h++) {
        const int tt = t + h * FFT_THREADS;
        float2 z[8];
#pragma unroll
        for (int r = 0; r < 8; r++) {
            const int n = tt + r * 1024;
            z[r] = make_float2((n < PMAX) ? hist[n] : 0.0f, 0.0f);
        }
        bf8<false>(b0, tt, 1, z[0], z[1], z[2], z[3], z[4], z[5], z[6], z[7], lut);
    }
    __syncthreads();
    stage_smem<false>(b0, b1, 8, lut);   __syncthreads();   // overwrites hist (consumed)
    stage_smem<false>(b1, b0, 64, lut);  __syncthreads();

    float2 sum[8], dif[8];
    last_pass<false, false>(b0, sum, dif);
#pragma unroll
    for (int r = 0; r < 8; r++) {
        const int i = t + r * 512;
        g_CNT[b][i]        = pk(sum[r]);
        g_CNT[b][i + 4096] = pk(dif[r]);
    }
}

// ---------------------------------------------------------------------------
// K2: spectral multiply fused into stage0 of the inverse FFT; fused + pruned
// last pass writes packed bf16x2 results (q in [0,3000)) straight to g_Gp.
// ---------------------------------------------------------------------------
__global__ void __launch_bounds__(FFT_THREADS, 2)
conv_kernel() {
    const int c = blockIdx.x;
    const int b = blockIdx.y;
    uint32_t* b0  = smu;
    uint32_t* b1  = smu + PADN;
    float2*   lut = (float2*)(smu + 2 * PADN);
    build_lut(lut);
    __syncthreads();

    const uint32_t* __restrict__ E = g_EMB[c];
    const uint32_t* __restrict__ T = g_CNT[b];

    // stage 0 (m=1) fused with pointwise spectral multiply
#pragma unroll
    for (int h = 0; h < 2; h++) {
        const int t = threadIdx.x + h * FFT_THREADS;
        float2 z[8];
#pragma unroll
        for (int r = 0; r < 8; r++) {
            const int n = t + r * 1024;
            z[r] = cmul(up(E[n]), up(T[n]));
        }
        bf8<true>(b0, t, 1, z[0], z[1], z[2], z[3], z[4], z[5], z[6], z[7], lut);
    }
    __syncthreads();
    stage_smem<true>(b0, b1, 8, lut);   __syncthreads();
    stage_smem<true>(b1, b0, 64, lut);  __syncthreads();

    // fused + pruned stage3 + radix-2 -> packed pruned global write
    float2 sum[8], dif[8];
    last_pass<true, true>(b0, sum, dif);
    const float inv = 1.0f / (float)NFFT;
    const int k = threadIdx.x;
#pragma unroll
    for (int r = 0; r < 8; r++) {
        if (r == 2 || r == 3) continue;        // pruned: q out of range
        const int i = k + r * 512;             // [0, 4096)
        if (i >= Mc) {                         // out[i] -> q = i - 2048  (r >= 4)
            const int q = i - Mc;
            g_Gp[b][q][c] = pk(make_float2(sum[r].x * inv, sum[r].y * inv));
        }
        if (i < PMAX - Mc) {                   // out[i+4096] -> q = i + 2048 (r <= 1)
            const int q = i + Mc;
            g_Gp[b][q][c] = pk(make_float2(dif[r].x * inv, dif[r].y * inv));
        }
    }
}

// ---------------------------------------------------------------------------
// K3: gather per output row + clamp-tail correction + add x, write out.
// Each thread handles 16 channels (two uint4 of packed G, 4 float4 of x/out)
// for higher memory-level parallelism.
// ---------------------------------------------------------------------------
__global__ void epilogue_kernel(const float4* __restrict__ x,
                                const float*  __restrict__ emb,
                                const int*    __restrict__ pos,
                                float4*       __restrict__ out) {
    const int v = blockIdx.x * blockDim.x + threadIdx.x;   // [0, B*S*D/16)
    const int d16 = v & 31;              // 16-channel group (32 per row)
    const int row = v >> 5;
    const int b   = row >> 11;
    const int q   = pos[row];

    // issue all independent loads up front
    const uint4 gpa = *reinterpret_cast<const uint4*>(&g_Gp[b][q][d16 * 8]);
    const uint4 gpb = *reinterpret_cast<const uint4*>(&g_Gp[b][q][d16 * 8 + 4]);
    const float4 x0 = x[v * 4 + 0];
    const float4 x1 = x[v * 4 + 1];
    const float4 x2 = x[v * 4 + 2];
    const float4 x3 = x[v * 4 + 3];
    const float4* e0p = reinterpret_cast<const float4*>(&emb[d16 * 16]);
    const float4* e1p = reinterpret_cast<const float4*>(&emb[(Vc - 1) * Dc + d16 * 16]);
    const float4 e00 = e0p[0], e01 = e0p[1], e02 = e0p[2], e03 = e0p[3];
    const float4 e10 = e1p[0], e11 = e1p[1], e12 = e1p[2], e13 = e1p[3];

    const float a0 = (float)Sc - g_pre[b][min(q + Mc, PMAX - 1)];
    const float a1 = (q >= Mc + 1) ? g_pre[b][q - Mc - 1] : 0.0f;
    const float invS = 1.0f / (float)Sc;

    const float2 g0 = up(gpa.x), g1 = up(gpa.y), g2 = up(gpa.z), g3 = up(gpa.w);
    const float2 g4 = up(gpb.x), g5 = up(gpb.y), g6 = up(gpb.z), g7 = up(gpb.w);

    float4 o0, o1, o2, o3;
    o0.x = x0.x + (g0.x + a0 * e00.x + a1 * e10.x) * invS;
    o0.y = x0.y + (g0.y + a0 * e00.y + a1 * e10.y) * invS;
    o0.z = x0.z + (g1.x + a0 * e00.z + a1 * e10.z) * invS;
    o0.w = x0.w + (g1.y + a0 * e00.w + a1 * e10.w) * invS;
    o1.x = x1.x + (g2.x + a0 * e01.x + a1 * e11.x) * invS;
    o1.y = x1.y + (g2.y + a0 * e01.y + a1 * e11.y) * invS;
    o1.z = x1.z + (g3.x + a0 * e01.z + a1 * e11.z) * invS;
    o1.w = x1.w + (g3.y + a0 * e01.w + a1 * e11.w) * invS;
    o2.x = x2.x + (g4.x + a0 * e02.x + a1 * e12.x) * invS;
    o2.y = x2.y + (g4.y + a0 * e02.y + a1 * e12.y) * invS;
    o2.z = x2.z + (g5.x + a0 * e02.z + a1 * e12.z) * invS;
    o2.w = x2.w + (g5.y + a0 * e02.w + a1 * e12.w) * invS;
    o3.x = x3.x + (g6.x + a0 * e03.x + a1 * e13.x) * invS;
    o3.y = x3.y + (g6.y + a0 * e03.y + a1 * e13.y) * invS;
    o3.z = x3.z + (g7.x + a0 * e03.z + a1 * e13.z) * invS;
    o3.w = x3.w + (g7.y + a0 * e03.w + a1 * e13.w) * invS;
    out[v * 4 + 0] = o0;
    out[v * 4 + 1] = o1;
    out[v * 4 + 2] = o2;
    out[v * 4 + 3] = o3;
}

// ---------------------------------------------------------------------------
// Launch
// ---------------------------------------------------------------------------
extern "C" void kernel_launch(void* const* d_in, const int* in_sizes, int n_in,
                              void* d_out, int out_size) {
    const float* x   = (const float*)d_in[0];
    const float* emb = (const float*)d_in[1];
    const int*   pos = (const int*)d_in[2];
    float*       out = (float*)d_out;

    cudaFuncSetAttribute(prep_kernel, cudaFuncAttributeMaxDynamicSharedMemorySize, FFT_SMEM);
    cudaFuncSetAttribute(conv_kernel, cudaFuncAttributeMaxDynamicSharedMemorySize, FFT_SMEM);

    transpose_kernel<<<dim3(NFFT / 32, CPAIRS / 32), dim3(32, 8)>>>(emb);
    prep_kernel<<<CPAIRS + Bc, FFT_THREADS, FFT_SMEM>>>(pos);
    conv_kernel<<<dim3(CPAIRS, Bc), FFT_THREADS, FFT_SMEM>>>();

    const int total_thr = Bc * Sc * Dc / 16;   // 262144
    epilogue_kernel<<<total_thr / 256, 256>>>((const float4*)x, emb, pos, (float4*)out);
}

// round 17
// speedup vs baseline: 1.1585x; 1.1585x over previous
#include <cuda_runtime.h>
#include <cuda_bf16.h>
#include <cstdint>

// Problem constants (fixed shapes from the reference)
#define Bc     4
#define Sc     2048
#define Dc     512
#define Mc     2048          // clip range
#define Vc     4097          // 2M+1 table rows
#define PMAX   3000          // positions in [0, 3000)
#define NFFT   8192
#define CPAIRS (Dc/2)        // 256 complex-packed channel pairs
#define FFT_THREADS 512
#define LUT_N  1024                          // u = W^jm, jm < NFFT/8 (fp32)
#define PADN   (NFFT + (NFFT >> 5))          // 8448 u32 per buffer
#define MAP(i) ((i) + ((i) >> 5))            // bank-conflict-free pad (4B elems)
#define FFT_SMEM (2 * PADN * 4 + LUT_N * 8)  // 75776 B -> 2 CTAs/SM

// ---------------------------------------------------------------------------
// Scratch (static device globals)
// ---------------------------------------------------------------------------
__device__ float2   g_ab[Bc * Sc];            // per-row (a0, a1) clamp weights
__device__ uint32_t g_CNT[Bc][NFFT];          // spectra of cnt (bf16x2: re,im)
__device__ uint32_t g_EMB[CPAIRS][NFFT];      // spectra of table column pairs
__device__ uint32_t g_EbfT[CPAIRS][NFFT];     // transposed packed emb columns
__device__ uint32_t g_Gp[Bc][PMAX][CPAIRS];   // interior result, packed bf16x2

// ---------------------------------------------------------------------------
// bf16x2 <-> float2 (re in low half, im in high half)
// ---------------------------------------------------------------------------
__device__ __forceinline__ float2 up(uint32_t v) {
    return make_float2(__uint_as_float(v << 16),
                       __uint_as_float(v & 0xFFFF0000u));
}
__device__ __forceinline__ uint32_t pk(float2 f) {
    uint32_t r;
    asm("cvt.rn.bf16x2.f32 %0, %1, %2;" : "=r"(r) : "f"(f.y), "f"(f.x));
    return r;
}

__device__ __forceinline__ float2 cmul(float2 a, float2 b) {
    return make_float2(a.x * b.x - a.y * b.y, a.x * b.y + a.y * b.x);
}
__device__ __forceinline__ float2 cadd(float2 a, float2 b) {
    return make_float2(a.x + b.x, a.y + b.y);
}
__device__ __forceinline__ float2 csub(float2 a, float2 b) {
    return make_float2(a.x - b.x, a.y - b.y);
}
template <bool INV>
__device__ __forceinline__ float2 mul_mi(float2 v) {   // * (-i) fwd, (+i) inv
    return INV ? make_float2(-v.y, v.x) : make_float2(v.y, -v.x);
}
#define RSQRT2 0.70710678118654752f
template <bool INV>
__device__ __forceinline__ float2 mul_w1(float2 v) {
    return INV ? make_float2((v.x - v.y) * RSQRT2, (v.y + v.x) * RSQRT2)
               : make_float2((v.x + v.y) * RSQRT2, (v.y - v.x) * RSQRT2);
}
template <bool INV>
__device__ __forceinline__ float2 mul_w3(float2 v) {
    return INV ? make_float2((-v.x - v.y) * RSQRT2, (v.x - v.y) * RSQRT2)
               : make_float2((v.y - v.x) * RSQRT2, (-v.x - v.y) * RSQRT2);
}

// ---------------------------------------------------------------------------
// Twiddle LUT (fp32): lut[t] = exp(-2*pi*i*t/NFFT), t in [0, NFFT/8)
// ---------------------------------------------------------------------------
__device__ __forceinline__ void build_lut(float2* lut) {
    const float w = -6.283185307179586f / (float)NFFT;
#pragma unroll
    for (int h = 0; h < LUT_N / FFT_THREADS; h++) {
        const int t = threadIdx.x + h * FFT_THREADS;
        float sn, cs;
        __sincosf(w * (float)t, &sn, &cs);
        lut[t] = make_float2(cs, sn);
    }
}

// ---------------------------------------------------------------------------
// Radix-8 core (no twiddles)
// ---------------------------------------------------------------------------
template <bool INV>
__device__ __forceinline__ void bf8_core(float2 y[8],
                                         float2 x0, float2 x1, float2 x2, float2 x3,
                                         float2 x4, float2 x5, float2 x6, float2 x7) {
    const float2 t0 = cadd(x0, x4);
    const float2 t1 = csub(x0, x4);
    const float2 t2 = cadd(x2, x6);
    const float2 t3 = mul_mi<INV>(csub(x2, x6));
    const float2 E0 = cadd(t0, t2);
    const float2 E1 = cadd(t1, t3);
    const float2 E2 = csub(t0, t2);
    const float2 E3 = csub(t1, t3);
    const float2 s0 = cadd(x1, x5);
    const float2 s1 = csub(x1, x5);
    const float2 s2 = cadd(x3, x7);
    const float2 s3 = mul_mi<INV>(csub(x3, x7));
    const float2 O0 = cadd(s0, s2);
    const float2 O1 = mul_w1<INV>(cadd(s1, s3));
    const float2 O2 = mul_mi<INV>(csub(s0, s2));
    const float2 O3 = mul_w3<INV>(csub(s1, s3));
    y[0] = cadd(E0, O0); y[1] = cadd(E1, O1);
    y[2] = cadd(E2, O2); y[3] = cadd(E3, O3);
    y[4] = csub(E0, O0); y[5] = csub(E1, O1);
    y[6] = csub(E2, O2); y[7] = csub(E3, O3);
}

// ---------------------------------------------------------------------------
// Radix-8 butterfly -> smem.
// ---------------------------------------------------------------------------
template <bool INV>
__device__ __forceinline__ void bf8(uint32_t* dst, int t, int m,
                                    float2 x0, float2 x1, float2 x2, float2 x3,
                                    float2 x4, float2 x5, float2 x6, float2 x7,
                                    const float2* __restrict__ lut) {
    const int k  = t & (m - 1);
    const int jm = t - k;
    float2 y[8];
    bf8_core<INV>(y, x0, x1, x2, x3, x4, x5, x6, x7);

    float2 u = lut[jm];
    if (INV) u.y = -u.y;
    const float2 u2 = cmul(u, u);
    const float2 u3 = cmul(u2, u);
    const float2 u4 = cmul(u2, u2);

    const int ob = t + 7 * jm;             // 8*j*m + k
    dst[MAP(ob + 0 * m)] = pk(y[0]);
    dst[MAP(ob + 1 * m)] = pk(cmul(u,  y[1]));
    dst[MAP(ob + 2 * m)] = pk(cmul(u2, y[2]));
    dst[MAP(ob + 3 * m)] = pk(cmul(u3, y[3]));
    dst[MAP(ob + 4 * m)] = pk(cmul(u4, y[4]));
    dst[MAP(ob + 5 * m)] = pk(cmul(cmul(u4, u),  y[5]));
    dst[MAP(ob + 6 * m)] = pk(cmul(cmul(u4, u2), y[6]));
    dst[MAP(ob + 7 * m)] = pk(cmul(cmul(u4, u3), y[7]));
}

// middle stage: smem -> smem (fully unrolled: keep 2-butterfly ILP)
template <bool INV>
__device__ __forceinline__ void stage_smem(const uint32_t* src, uint32_t* dst,
                                           int m, const float2* __restrict__ lut) {
#pragma unroll
    for (int h = 0; h < 2; h++) {
        const int t = threadIdx.x + h * FFT_THREADS;   // [0, 1024)
        bf8<INV>(dst, t, m,
                 up(src[MAP(t + 0 * 1024)]), up(src[MAP(t + 1 * 1024)]),
                 up(src[MAP(t + 2 * 1024)]), up(src[MAP(t + 3 * 1024)]),
                 up(src[MAP(t + 4 * 1024)]), up(src[MAP(t + 5 * 1024)]),
                 up(src[MAP(t + 6 * 1024)]), up(src[MAP(t + 7 * 1024)]),
                 lut);
    }
}

// ---------------------------------------------------------------------------
// Fused last pass: stage 3 (m=512, j=0 & j=1 in registers) + final radix-2.
// j=1 twiddle W^512r = exp(-i*pi*r/8): compile-time constants.
// PRUNE: skip r in {2,3}.
// ---------------------------------------------------------------------------
template <bool INV, bool PRUNE>
__device__ __forceinline__ void last_pass(const uint32_t* src,
                                          float2 sum[8], float2 dif[8]) {
    const int k = threadIdx.x;
    float2 A[8];
    bf8_core<INV>(A,
                  up(src[MAP(k + 0 * 1024)]), up(src[MAP(k + 1 * 1024)]),
                  up(src[MAP(k + 2 * 1024)]), up(src[MAP(k + 3 * 1024)]),
                  up(src[MAP(k + 4 * 1024)]), up(src[MAP(k + 5 * 1024)]),
                  up(src[MAP(k + 6 * 1024)]), up(src[MAP(k + 7 * 1024)]));
    float2 B[8];
    {
        const int t = k + 512;
        bf8_core<INV>(B,
                      up(src[MAP(t + 0 * 1024)]), up(src[MAP(t + 1 * 1024)]),
                      up(src[MAP(t + 2 * 1024)]), up(src[MAP(t + 3 * 1024)]),
                      up(src[MAP(t + 4 * 1024)]), up(src[MAP(t + 5 * 1024)]),
                      up(src[MAP(t + 6 * 1024)]), up(src[MAP(t + 7 * 1024)]));
    }
    const float TWC[8] = { 1.0f,  0.92387953251f,  0.70710678119f,  0.38268343236f,
                           0.0f, -0.38268343236f, -0.70710678119f, -0.92387953251f };
    const float TWS[8] = { 0.0f, -0.38268343236f, -0.70710678119f, -0.92387953251f,
                          -1.0f, -0.92387953251f, -0.70710678119f, -0.38268343236f };
#pragma unroll
    for (int r = 0; r < 8; r++) {
        if (PRUNE && (r == 2 || r == 3)) continue;
        const float2 w  = make_float2(TWC[r], INV ? -TWS[r] : TWS[r]);
        const float2 Br = cmul(w, B[r]);
        sum[r] = cadd(A[r], Br);
        dif[r] = csub(A[r], Br);
    }
}

extern __shared__ uint32_t smu[];

// ---------------------------------------------------------------------------
// K0: transpose emb [4097][512] fp32 -> g_EbfT[c][n] packed bf16x2, zero-pad
// ---------------------------------------------------------------------------
__global__ void transpose_kernel(const float* __restrict__ emb) {
    __shared__ uint32_t tile[32][33];
    const int n0 = blockIdx.x * 32;
    const int c0 = blockIdx.y * 32;
    const int tx = threadIdx.x;
    for (int r = threadIdx.y; r < 32; r += 8) {
        const int n = n0 + r;
        uint32_t v = 0;
        if (n < Vc) {
            const float2 e = *reinterpret_cast<const float2*>(
                &emb[n * Dc + 2 * (c0 + tx)]);
            v = pk(e);
        }
        tile[r][tx] = v;
    }
    __syncthreads();
    for (int r = threadIdx.y; r < 32; r += 8)
        g_EbfT[c0 + r][n0 + tx] = tile[tx][r];
}

// ---------------------------------------------------------------------------
// K1 (merged prep): grid = CPAIRS + Bc blocks.
//  blocks [0, CPAIRS):    forward FFT of table column pair c -> g_EMB[c]
//  blocks [CPAIRS, +Bc):  histogram + scan + per-row (a0,a1) + count FFT
// ---------------------------------------------------------------------------
__global__ void __launch_bounds__(FFT_THREADS, 2)
prep_kernel(const int* __restrict__ pos) {
    uint32_t* b0  = smu;
    uint32_t* b1  = smu + PADN;
    float2*   lut = (float2*)(smu + 2 * PADN);

    if (blockIdx.x < CPAIRS) {
        const int c = blockIdx.x;
        build_lut(lut);
        __syncthreads();

        const uint32_t* __restrict__ Ec = g_EbfT[c];
        // stage 0 (m=1) fused with coalesced global load
#pragma unroll
        for (int h = 0; h < 2; h++) {
            const int t = threadIdx.x + h * FFT_THREADS;
            float2 z[8];
#pragma unroll
            for (int r = 0; r < 8; r++)
                z[r] = up(Ec[t + r * 1024]);
            bf8<false>(b0, t, 1, z[0], z[1], z[2], z[3], z[4], z[5], z[6], z[7], lut);
        }
        __syncthreads();
        stage_smem<false>(b0, b1, 8, lut);   __syncthreads();
        stage_smem<false>(b1, b0, 64, lut);  __syncthreads();

        // fused stage3 + radix-2 -> global
        float2 sum[8], dif[8];
        last_pass<false, false>(b0, sum, dif);
        const int k = threadIdx.x;
#pragma unroll
        for (int r = 0; r < 8; r++) {
            const int i = k + r * 512;
            g_EMB[c][i]        = pk(sum[r]);
            g_EMB[c][i + 4096] = pk(dif[r]);
        }
        return;
    }

    // ---------------- count-histogram blocks ----------------
    const int b = blockIdx.x - CPAIRS;
    const int t = threadIdx.x;
    float* hist   = (float*)b1;              // 3072 floats in b1 region
    float* tsum   = (float*)b0;              // 512 partial sums (b0[0:512))
    float* pre_sh = (float*)b0 + 1024;       // 3000 floats (b0[1024:4024))

    for (int p = t; p < 3072; p += FFT_THREADS) hist[p] = 0.0f;
    __syncthreads();
    for (int i = t; i < Sc; i += FFT_THREADS)
        atomicAdd(&hist[pos[b * Sc + i]], 1.0f);
    __syncthreads();

    // inclusive prefix scan: 6 bins per thread
    float v[6];
    float s = 0.0f;
#pragma unroll
    for (int j = 0; j < 6; j++) { v[j] = hist[6 * t + j]; s += v[j]; }
    tsum[t] = s;
    __syncthreads();
    for (int off = 1; off < FFT_THREADS; off <<= 1) {
        const float add = (t >= off) ? tsum[t - off] : 0.0f;
        __syncthreads();
        tsum[t] += add;
        __syncthreads();
    }
    float run = tsum[t] - s;   // exclusive
#pragma unroll
    for (int j = 0; j < 6; j++) {
        run += v[j];
        const int p = 6 * t + j;
        if (p < PMAX) pre_sh[p] = run;
    }
    __syncthreads();

    // per-row clamp weights: a0 = #(p > q+M), a1 = #(p < q-M)
    for (int i = t; i < Sc; i += FFT_THREADS) {
        const int q = pos[b * Sc + i];
        const float a0 = (float)Sc - pre_sh[min(q + Mc, PMAX - 1)];
        const float a1 = (q >= Mc + 1) ? pre_sh[q - Mc - 1] : 0.0f;
        g_ab[b * Sc + i] = make_float2(a0, a1);
    }
    __syncthreads();

    // forward FFT of the histogram (stage0 reads hist directly from smem)
    build_lut(lut);
    __syncthreads();
#pragma unroll
    for (int h = 0; h < 2; h++) {
        const int tt = t + h * FFT_THREADS;
        float2 z[8];
#pragma unroll
        for (int r = 0; r < 8; r++) {
            const int n = tt + r * 1024;
            z[r] = make_float2((n < PMAX) ? hist[n] : 0.0f, 0.0f);
        }
        bf8<false>(b0, tt, 1, z[0], z[1], z[2], z[3], z[4], z[5], z[6], z[7], lut);
    }
    __syncthreads();
    stage_smem<false>(b0, b1, 8, lut);   __syncthreads();   // overwrites hist (consumed)
    stage_smem<false>(b1, b0, 64, lut);  __syncthreads();

    float2 sum[8], dif[8];
    last_pass<false, false>(b0, sum, dif);
#pragma unroll
    for (int r = 0; r < 8; r++) {
        const int i = t + r * 512;
        g_CNT[b][i]        = pk(sum[r]);
        g_CNT[b][i + 4096] = pk(dif[r]);
    }
}

// ---------------------------------------------------------------------------
// K2: spectral multiply fused into stage0 of the inverse FFT; fused + pruned
// last pass writes packed bf16x2 results (q in [0,3000)) straight to g_Gp.
// ---------------------------------------------------------------------------
__global__ void __launch_bounds__(FFT_THREADS, 2)
conv_kernel() {
    const int c = blockIdx.x;
    const int b = blockIdx.y;
    uint32_t* b0  = smu;
    uint32_t* b1  = smu + PADN;
    float2*   lut = (float2*)(smu + 2 * PADN);
    build_lut(lut);
    __syncthreads();

    const uint32_t* __restrict__ E = g_EMB[c];
    const uint32_t* __restrict__ T = g_CNT[b];

    // stage 0 (m=1) fused with pointwise spectral multiply
#pragma unroll
    for (int h = 0; h < 2; h++) {
        const int t = threadIdx.x + h * FFT_THREADS;
        float2 z[8];
#pragma unroll
        for (int r = 0; r < 8; r++) {
            const int n = t + r * 1024;
            z[r] = cmul(up(E[n]), up(T[n]));
        }
        bf8<true>(b0, t, 1, z[0], z[1], z[2], z[3], z[4], z[5], z[6], z[7], lut);
    }
    __syncthreads();
    stage_smem<true>(b0, b1, 8, lut);   __syncthreads();
    stage_smem<true>(b1, b0, 64, lut);  __syncthreads();

    // fused + pruned stage3 + radix-2 -> packed pruned global write
    float2 sum[8], dif[8];
    last_pass<true, true>(b0, sum, dif);
    const float inv = 1.0f / (float)NFFT;
    const int k = threadIdx.x;
#pragma unroll
    for (int r = 0; r < 8; r++) {
        if (r == 2 || r == 3) continue;        // pruned: q out of range
        const int i = k + r * 512;             // [0, 4096)
        if (i >= Mc) {                         // out[i] -> q = i - 2048  (r >= 4)
            const int q = i - Mc;
            g_Gp[b][q][c] = pk(make_float2(sum[r].x * inv, sum[r].y * inv));
        }
        if (i < PMAX - Mc) {                   // out[i+4096] -> q = i + 2048 (r <= 1)
            const int q = i + Mc;
            g_Gp[b][q][c] = pk(make_float2(dif[r].x * inv, dif[r].y * inv));
        }
    }
}

// ---------------------------------------------------------------------------
// K3: gather per output row + clamp-tail correction + add x, write out.
// 8 channels/thread (R15 proven shape); (a0,a1) read from precomputed g_ab
// (row-indexed, independent of the pos load -> only one dependent-load level).
// ---------------------------------------------------------------------------
__global__ void epilogue_kernel(const float4* __restrict__ x,
                                const float*  __restrict__ emb,
                                const int*    __restrict__ pos,
                                float4*       __restrict__ out) {
    const int v = blockIdx.x * blockDim.x + threadIdx.x;   // [0, B*S*D/8)
    const int d8  = v & 63;              // 8-channel group
    const int row = v >> 6;
    const int b   = row >> 11;
    const int q   = pos[row];

    const float2 ab = g_ab[row];
    const float a0 = ab.x;
    const float a1 = ab.y;
    const float invS = 1.0f / (float)Sc;

    const uint4 gp = *reinterpret_cast<const uint4*>(&g_Gp[b][q][d8 * 4]);
    const float2 g0 = up(gp.x), g1 = up(gp.y), g2 = up(gp.z), g3 = up(gp.w);

    const float4 xa = x[v * 2];
    const float4 xb = x[v * 2 + 1];
    const float4 e0a = *reinterpret_cast<const float4*>(&emb[d8 * 8]);
    const float4 e0b = *reinterpret_cast<const float4*>(&emb[d8 * 8 + 4]);
    const float4 e1a = *reinterpret_cast<const float4*>(&emb[(Vc - 1) * Dc + d8 * 8]);
    const float4 e1b = *reinterpret_cast<const float4*>(&emb[(Vc - 1) * Dc + d8 * 8 + 4]);

    float4 oa, ob;
    oa.x = xa.x + (g0.x + a0 * e0a.x + a1 * e1a.x) * invS;
    oa.y = xa.y + (g0.y + a0 * e0a.y + a1 * e1a.y) * invS;
    oa.z = xa.z + (g1.x + a0 * e0a.z + a1 * e1a.z) * invS;
    oa.w = xa.w + (g1.y + a0 * e0a.w + a1 * e1a.w) * invS;
    ob.x = xb.x + (g2.x + a0 * e0b.x + a1 * e1b.x) * invS;
    ob.y = xb.y + (g2.y + a0 * e0b.y + a1 * e1b.y) * invS;
    ob.z = xb.z + (g3.x + a0 * e0b.z + a1 * e1b.z) * invS;
    ob.w = xb.w + (g3.y + a0 * e0b.w + a1 * e1b.w) * invS;
    out[v * 2]     = oa;
    out[v * 2 + 1] = ob;
}

// ---------------------------------------------------------------------------
// Launch
// ---------------------------------------------------------------------------
extern "C" void kernel_launch(void* const* d_in, const int* in_sizes, int n_in,
                              void* d_out, int out_size) {
    const float* x   = (const float*)d_in[0];
    const float* emb = (const float*)d_in[1];
    const int*   pos = (const int*)d_in[2];
    float*       out = (float*)d_out;

    cudaFuncSetAttribute(prep_kernel, cudaFuncAttributeMaxDynamicSharedMemorySize, FFT_SMEM);
    cudaFuncSetAttribute(conv_kernel, cudaFuncAttributeMaxDynamicSharedMemorySize, FFT_SMEM);

    transpose_kernel<<<dim3(NFFT / 32, CPAIRS / 32), dim3(32, 8)>>>(emb);
    prep_kernel<<<CPAIRS + Bc, FFT_THREADS, FFT_SMEM>>>(pos);
    conv_kernel<<<dim3(CPAIRS, Bc), FFT_THREADS, FFT_SMEM>>>();

    const int total_thr = Bc * Sc * Dc / 8;    // 524288
    epilogue_kernel<<<total_thr / 256, 256>>>((const float4*)x, emb, pos, (float4*)out);
}